// round 7
// baseline (speedup 1.0000x reference)
#include <cuda_runtime.h>

// ModelFilter: y = gain * clip(IIR2(FIR2(x)), -1, 1)
// 3-kernel chunked parallel scan. Register-prefetch software pipelining
// (no cp.async / no inline PTX), double-buffered swizzled smem staging.
//   CHUNK=128 samples/thread-chunk, 2048 chunks/row, 131072 chunk-threads.
//   phase1: zero-IC chunk end states (step-2 companion form recurrence)
//   phase2: per-row Kogge-Stone scan; closed-form fp64 matrix powers
//   phase3: replay from true init (x re-read hits L2), clip*gain, stcs out.

#define BATCH 64
#define TLEN  262144
#define CHUNK 128
#define CPR   (TLEN / CHUNK)          // 2048 chunks per row
#define TOTAL_CHUNKS (BATCH * CPR)    // 131072
#define CPB   128                     // chunk-threads per block
#define NBLK  (TOTAL_CHUNKS / CPB)    // 1024 blocks
#define WIN   32                      // samples per window = 128B smem row
#define NW    (CHUNK / WIN)           // 4 windows

__device__ float2 g_d[TOTAL_CHUNKS];     // phase-1 zero-IC end states
__device__ float2 g_init[TOTAL_CHUNKS];  // phase-2 true initial states

// ---------------------------------------------------------------------------
// Phase 1: zero-IC chunk recurrence -> end states.
//   Pipeline: prefetch window w+1 into registers while computing window w.
//   Double-buffered smem => one __syncthreads per window.
__global__ void __launch_bounds__(CPB, 6)
phase1_kernel(const float* __restrict__ x,
              const float* __restrict__ ac,
              const float* __restrict__ bcf)
{
    __shared__ float sb[2][CPB * WIN];       // 2 x 16 KB

    const int t   = threadIdx.x;
    const int bg  = blockIdx.x * CPB;
    const int g   = bg + t;
    const int row = bg >> 11;                // CPR = 2048
    const int bcc = bg & (CPR - 1);
    const int cir = bcc + t;

    const float a0 = __ldg(&ac[0]);
    const float a1 = __ldg(&ac[1]) / a0, a2 = __ldg(&ac[2]) / a0;
    const float b0 = __ldg(&bcf[0]) / a0, b1 = __ldg(&bcf[1]) / a0,
                b2 = __ldg(&bcf[2]) / a0;
    const float na1 = -a1, na2 = -a2;
    const float c00 = fmaf(a1, a1, -a2);     // a1^2 - a2
    const float c01 = a1 * a2;

    const float* xr   = x + (size_t)row * TLEN;
    const float4* xb4 = (const float4*)(xr + (size_t)bcc * CHUNK);

    float x1 = 0.0f, x2 = 0.0f;
    if (cir > 0) { int n0 = cir * CHUNK; x1 = xr[n0 - 1]; x2 = xr[n0 - 2]; }
    float y1 = 0.0f, y2 = 0.0f;

    float4 r[8];
    #pragma unroll
    for (int j = 0; j < 8; j++) {            // prefetch window 0 (coalesced)
        int idx = t + CPB * j;
        r[j] = __ldg(xb4 + (idx >> 3) * (CHUNK / 4) + (idx & 7));
    }

    for (int w = 0; w < NW; w++) {
        // stage prefetched window w into smem (swizzled, conflict-free)
        #pragma unroll
        for (int j = 0; j < 8; j++) {
            int idx = t + CPB * j;
            int c   = idx >> 3;
            int sl  = idx & 7;
            *(float4*)&sb[w & 1][c * WIN + (((sl + c) & 7) << 2)] = r[j];
        }
        __syncthreads();

        // issue next window's loads; they land during compute
        if (w + 1 < NW) {
            #pragma unroll
            for (int j = 0; j < 8; j++) {
                int idx = t + CPB * j;
                r[j] = __ldg(xb4 + (idx >> 3) * (CHUNK / 4) + (w + 1) * 8
                                 + (idx & 7));
            }
        }

        const float* rowp = &sb[w & 1][t * WIN];
        #pragma unroll
        for (int gq = 0; gq < 8; gq++) {
            float4 v = *(const float4*)&rowp[((gq + t) & 7) << 2];
            {
                float f0 = fmaf(b2, x2, fmaf(b1, x1, b0 * v.x));
                float f1 = fmaf(b2, x1, fmaf(b1, v.x, b0 * v.y));
                float F1 = fmaf(na1, f0, f1);
                float t0 = fmaf(na2, y2, f0);
                float t1 = fmaf(c01, y2, F1);
                float yA = fmaf(na1, y1, t0);
                float yB = fmaf(c00, y1, t1);
                y2 = yA; y1 = yB; x2 = v.x; x1 = v.y;
            }
            {
                float f0 = fmaf(b2, x2, fmaf(b1, x1, b0 * v.z));
                float f1 = fmaf(b2, x1, fmaf(b1, v.z, b0 * v.w));
                float F1 = fmaf(na1, f0, f1);
                float t0 = fmaf(na2, y2, f0);
                float t1 = fmaf(c01, y2, F1);
                float yA = fmaf(na1, y1, t0);
                float yB = fmaf(c00, y1, t1);
                y2 = yA; y1 = yB; x2 = v.z; x1 = v.w;
            }
        }
        // no trailing sync: next STS targets the other buffer, and the
        // barrier above prevents any thread from being 2 windows ahead.
    }
    g_d[g] = make_float2(y1, y2);
}

// ---------------------------------------------------------------------------
// Phase 2: per-row scan. 1024 threads, 2 chunks/thread (pair-combine with A,
// then 10-level Kogge-Stone with powers of B = A^2). Closed-form powers:
//   M^n = [[U_n, -a2*U_{n-1}], [U_{n-1}, -a2*U_{n-2}]],
//   U_m = r^m sin((m+1)theta)/sin(theta), r = sqrt(a2), cos(theta)=-a1/(2r).
__global__ void __launch_bounds__(1024)
phase2_kernel(const float* __restrict__ ac)
{
    __shared__ float2 s[1024];
    __shared__ float4 sA;
    __shared__ float4 sP[10];

    const int t   = threadIdx.x;
    const int row = blockIdx.x;

    if (t <= 10) {
        double a0 = (double)ac[0];
        double a1 = (double)ac[1] / a0;
        double a2 = (double)ac[2] / a0;
        double r  = sqrt(a2);
        double ct = -a1 / (2.0 * r);
        double th = acos(ct);
        double st = sqrt(fmax(1.0 - ct * ct, 1e-300));
        double n  = (t < 10) ? (double)(256 << t) : 128.0; // sP[k]=M^(256*2^k); sA=M^128
        double rn1 = exp((n - 1.0) * log(r));              // r^(n-1)
        double Sn  = sin(n * th) / st;
        double Snp = sin((n + 1.0) * th) / st;
        double Snm = sin((n - 1.0) * th) / st;
        float4 P;
        P.x = (float)( rn1 * r * Snp);     //  U_n
        P.y = (float)(-rn1 * r * r * Sn);  // -a2*U_{n-1}
        P.z = (float)( rn1 * Sn);          //  U_{n-1}
        P.w = (float)(-rn1 * r * Snm);     // -a2*U_{n-2}
        if (t < 10) sP[t] = P; else sA = P;
    }
    __syncthreads();

    const float4 A = sA;
    float2 d0 = g_d[row * CPR + 2 * t];
    float2 d1 = g_d[row * CPR + 2 * t + 1];
    float2 v;
    v.x = fmaf(A.x, d0.x, fmaf(A.y, d0.y, d1.x));
    v.y = fmaf(A.z, d0.x, fmaf(A.w, d0.y, d1.y));
    s[t] = v;
    __syncthreads();

    #pragma unroll
    for (int k = 0; k < 10; k++) {
        const int o = 1 << k;
        float4 P = sP[k];
        float2 u = (t >= o) ? s[t - o] : make_float2(0.0f, 0.0f);
        __syncthreads();
        if (t >= o) {
            v.x = fmaf(P.x, u.x, fmaf(P.y, u.y, v.x));
            v.y = fmaf(P.z, u.x, fmaf(P.w, u.y, v.y));
        }
        s[t] = v;
        __syncthreads();
    }

    // s[t] = true end state of chunk 2t+1.
    float2 Ep = (t == 0) ? make_float2(0.0f, 0.0f) : s[t - 1];
    float2 i1;   // init of chunk 2t+1 = end of chunk 2t = d0 + A*Ep
    i1.x = fmaf(A.x, Ep.x, fmaf(A.y, Ep.y, d0.x));
    i1.y = fmaf(A.z, Ep.x, fmaf(A.w, Ep.y, d0.y));
    g_init[row * CPR + 2 * t]     = Ep;
    g_init[row * CPR + 2 * t + 1] = i1;
}

// ---------------------------------------------------------------------------
// Phase 3: replay from true initial state; clip*gain written in place into
// the staging buffer, then cooperatively streamed out. Same pipelining.
__global__ void __launch_bounds__(CPB, 6)
phase3_kernel(const float* __restrict__ x, float* __restrict__ out,
              const float* __restrict__ ac, const float* __restrict__ bcf,
              const float* __restrict__ gain)
{
    __shared__ float sb[2][CPB * WIN];

    const int t   = threadIdx.x;
    const int bg  = blockIdx.x * CPB;
    const int g   = bg + t;
    const int row = bg >> 11;
    const int bcc = bg & (CPR - 1);
    const int cir = bcc + t;

    const float a0 = __ldg(&ac[0]);
    const float a1 = __ldg(&ac[1]) / a0, a2 = __ldg(&ac[2]) / a0;
    const float b0 = __ldg(&bcf[0]) / a0, b1 = __ldg(&bcf[1]) / a0,
                b2 = __ldg(&bcf[2]) / a0;
    const float na1 = -a1, na2 = -a2;
    const float c00 = fmaf(a1, a1, -a2);
    const float c01 = a1 * a2;
    const float gn  = __ldg(&gain[0]);

    const float* xr   = x + (size_t)row * TLEN;
    const float4* xb4 = (const float4*)(xr + (size_t)bcc * CHUNK);
    float4* ob4 = (float4*)(out + (size_t)row * TLEN + (size_t)bcc * CHUNK);

    float x1 = 0.0f, x2 = 0.0f;
    if (cir > 0) { int n0 = cir * CHUNK; x1 = xr[n0 - 1]; x2 = xr[n0 - 2]; }

    float2 ini = __ldg(&g_init[g]);
    float y1 = ini.x, y2 = ini.y;

    float4 r[8];
    #pragma unroll
    for (int j = 0; j < 8; j++) {
        int idx = t + CPB * j;
        r[j] = __ldg(xb4 + (idx >> 3) * (CHUNK / 4) + (idx & 7));
    }

    for (int w = 0; w < NW; w++) {
        #pragma unroll
        for (int j = 0; j < 8; j++) {
            int idx = t + CPB * j;
            int c   = idx >> 3;
            int sl  = idx & 7;
            *(float4*)&sb[w & 1][c * WIN + (((sl + c) & 7) << 2)] = r[j];
        }
        __syncthreads();

        if (w + 1 < NW) {
            #pragma unroll
            for (int j = 0; j < 8; j++) {
                int idx = t + CPB * j;
                r[j] = __ldg(xb4 + (idx >> 3) * (CHUNK / 4) + (w + 1) * 8
                                 + (idx & 7));
            }
        }

        float* rowp = &sb[w & 1][t * WIN];
        #pragma unroll
        for (int gq = 0; gq < 8; gq++) {
            float4* slot = (float4*)&rowp[((gq + t) & 7) << 2];
            float4 v = *slot;
            float4 o;
            {
                float f0 = fmaf(b2, x2, fmaf(b1, x1, b0 * v.x));
                float f1 = fmaf(b2, x1, fmaf(b1, v.x, b0 * v.y));
                float F1 = fmaf(na1, f0, f1);
                float t0 = fmaf(na2, y2, f0);
                float t1 = fmaf(c01, y2, F1);
                float yA = fmaf(na1, y1, t0);
                float yB = fmaf(c00, y1, t1);
                y2 = yA; y1 = yB; x2 = v.x; x1 = v.y;
                o.x = fminf(fmaxf(yA, -1.0f), 1.0f) * gn;
                o.y = fminf(fmaxf(yB, -1.0f), 1.0f) * gn;
            }
            {
                float f0 = fmaf(b2, x2, fmaf(b1, x1, b0 * v.z));
                float f1 = fmaf(b2, x1, fmaf(b1, v.z, b0 * v.w));
                float F1 = fmaf(na1, f0, f1);
                float t0 = fmaf(na2, y2, f0);
                float t1 = fmaf(c01, y2, F1);
                float yA = fmaf(na1, y1, t0);
                float yB = fmaf(c00, y1, t1);
                y2 = yA; y1 = yB; x2 = v.z; x1 = v.w;
                o.z = fminf(fmaxf(yA, -1.0f), 1.0f) * gn;
                o.w = fminf(fmaxf(yB, -1.0f), 1.0f) * gn;
            }
            *slot = o;   // in-place: own row only
        }
        __syncthreads();   // all rows computed before cooperative store

        const float* bufp = &sb[w & 1][0];
        #pragma unroll
        for (int j = 0; j < 8; j++) {
            int idx = t + CPB * j;
            int c   = idx >> 3;
            int sl  = idx & 7;
            float4 v = *(const float4*)&bufp[c * WIN + (((sl + c) & 7) << 2)];
            __stcs(ob4 + c * (CHUNK / 4) + w * 8 + sl, v);
        }
        // no trailing sync: next STS targets the other buffer, and the two
        // barriers above prevent any thread from being 2 windows ahead.
    }
}

// ---------------------------------------------------------------------------
extern "C" void kernel_launch(void* const* d_in, const int* in_sizes, int n_in,
                              void* d_out, int out_size)
{
    const float* x    = (const float*)d_in[0];
    const float* a    = (const float*)d_in[1];
    const float* b    = (const float*)d_in[2];
    const float* gain = (const float*)d_in[3];
    float* out = (float*)d_out;

    phase1_kernel<<<NBLK, CPB>>>(x, a, b);
    phase2_kernel<<<BATCH, 1024>>>(a);
    phase3_kernel<<<NBLK, CPB>>>(x, out, a, b, gain);
}

// round 8
// speedup vs baseline: 1.2236x; 1.2236x over previous
#include <cuda_runtime.h>

// ModelFilter: y = gain * clip(IIR2(FIR2(x)), -1, 1)
// 3-kernel chunked parallel scan with PER-WARP staging (no block barriers
// in the hot loops -> no barrier convoy).
//   CHUNK=128 samples/thread-chunk, 2048 chunks/row, 131072 chunk-threads.
//   phase1: zero-IC chunk end states (step-2 companion form recurrence)
//   phase2: per-row Kogge-Stone scan; closed-form fp64 matrix powers
//   phase3: replay from true init (x re-read hits L2), clip*gain, stcs out.

#define BATCH 64
#define TLEN  262144
#define CHUNK 128
#define CPR   (TLEN / CHUNK)          // 2048 chunks per row
#define TOTAL_CHUNKS (BATCH * CPR)    // 131072
#define CPB   128                     // chunk-threads per block (4 warps)
#define NBLK  (TOTAL_CHUNKS / CPB)    // 1024 blocks
#define WIN   32                      // samples per window = 128B smem row
#define NW    (CHUNK / WIN)           // 4 windows

__device__ float2 g_d[TOTAL_CHUNKS];     // phase-1 zero-IC end states
__device__ float2 g_init[TOTAL_CHUNKS];  // phase-2 true initial states

// ---------------------------------------------------------------------------
// Phase 1: zero-IC chunk recurrence -> end states. Per-warp staging.
__global__ void __launch_bounds__(CPB, 8)
phase1_kernel(const float* __restrict__ x,
              const float* __restrict__ ac,
              const float* __restrict__ bcf)
{
    __shared__ float sb[CPB / 32][32 * WIN];    // 4 KB per warp, 16 KB total

    const int t    = threadIdx.x;
    const int wu   = t >> 5;
    const int lane = t & 31;
    const int bg   = blockIdx.x * CPB;
    const int g    = bg + t;
    const int row  = bg >> 11;                  // CPR = 2048
    const int bcc  = bg & (CPR - 1);
    const int cir  = bcc + t;

    const float a0 = __ldg(&ac[0]);
    const float a1 = __ldg(&ac[1]) / a0, a2 = __ldg(&ac[2]) / a0;
    const float b0 = __ldg(&bcf[0]) / a0, b1 = __ldg(&bcf[1]) / a0,
                b2 = __ldg(&bcf[2]) / a0;
    const float na1 = -a1, na2 = -a2;
    const float c00 = fmaf(a1, a1, -a2);        // a1^2 - a2
    const float c01 = a1 * a2;

    const float* xr   = x + (size_t)row * TLEN;
    const float4* xw4 =
        (const float4*)(xr + (size_t)(bcc + wu * 32) * CHUNK);
    float* sw = &sb[wu][0];

    float x1 = 0.0f, x2 = 0.0f;
    if (cir > 0) { int n0 = cir * CHUNK; x1 = xr[n0 - 1]; x2 = xr[n0 - 2]; }
    float y1 = 0.0f, y2 = 0.0f;

    for (int w = 0; w < NW; w++) {
        // warp-cooperative coalesced load of this warp's 32 chunks' window
        #pragma unroll
        for (int j = 0; j < 8; j++) {
            int idx = lane + 32 * j;
            int c   = idx >> 3;
            int sl  = idx & 7;
            float4 v = __ldg(xw4 + c * (CHUNK / 4) + w * 8 + sl);
            *(float4*)&sw[c * WIN + (((sl + c) & 7) << 2)] = v;
        }
        __syncwarp();

        const float* rowp = &sw[lane * WIN];
        #pragma unroll
        for (int gq = 0; gq < 8; gq++) {
            float4 v = *(const float4*)&rowp[((gq + lane) & 7) << 2];
            {
                float f0 = fmaf(b2, x2, fmaf(b1, x1, b0 * v.x));
                float f1 = fmaf(b2, x1, fmaf(b1, v.x, b0 * v.y));
                float F1 = fmaf(na1, f0, f1);
                float t0 = fmaf(na2, y2, f0);
                float t1 = fmaf(c01, y2, F1);
                float yA = fmaf(na1, y1, t0);
                float yB = fmaf(c00, y1, t1);
                y2 = yA; y1 = yB; x2 = v.x; x1 = v.y;
            }
            {
                float f0 = fmaf(b2, x2, fmaf(b1, x1, b0 * v.z));
                float f1 = fmaf(b2, x1, fmaf(b1, v.z, b0 * v.w));
                float F1 = fmaf(na1, f0, f1);
                float t0 = fmaf(na2, y2, f0);
                float t1 = fmaf(c01, y2, F1);
                float yA = fmaf(na1, y1, t0);
                float yB = fmaf(c00, y1, t1);
                y2 = yA; y1 = yB; x2 = v.z; x1 = v.w;
            }
        }
        __syncwarp();   // all lanes done reading before next window's stores
    }
    g_d[g] = make_float2(y1, y2);
}

// ---------------------------------------------------------------------------
// Phase 2: per-row scan. 1024 threads, 2 chunks/thread (pair-combine with A,
// then 10-level Kogge-Stone with powers of B = A^2). Closed-form powers:
//   M^n = [[U_n, -a2*U_{n-1}], [U_{n-1}, -a2*U_{n-2}]],
//   U_m = r^m sin((m+1)theta)/sin(theta), r = sqrt(a2), cos(theta)=-a1/(2r).
__global__ void __launch_bounds__(1024)
phase2_kernel(const float* __restrict__ ac)
{
    __shared__ float2 s[1024];
    __shared__ float4 sA;
    __shared__ float4 sP[10];

    const int t   = threadIdx.x;
    const int row = blockIdx.x;

    if (t <= 10) {
        double a0 = (double)ac[0];
        double a1 = (double)ac[1] / a0;
        double a2 = (double)ac[2] / a0;
        double r  = sqrt(a2);
        double ct = -a1 / (2.0 * r);
        double th = acos(ct);
        double st = sqrt(fmax(1.0 - ct * ct, 1e-300));
        double n  = (t < 10) ? (double)(256 << t) : 128.0; // sP[k]=M^(256*2^k); sA=M^128
        double rn1 = exp((n - 1.0) * log(r));              // r^(n-1)
        double Sn  = sin(n * th) / st;
        double Snp = sin((n + 1.0) * th) / st;
        double Snm = sin((n - 1.0) * th) / st;
        float4 P;
        P.x = (float)( rn1 * r * Snp);
        P.y = (float)(-rn1 * r * r * Sn);
        P.z = (float)( rn1 * Sn);
        P.w = (float)(-rn1 * r * Snm);
        if (t < 10) sP[t] = P; else sA = P;
    }
    __syncthreads();

    const float4 A = sA;
    float2 d0 = g_d[row * CPR + 2 * t];
    float2 d1 = g_d[row * CPR + 2 * t + 1];
    float2 v;
    v.x = fmaf(A.x, d0.x, fmaf(A.y, d0.y, d1.x));
    v.y = fmaf(A.z, d0.x, fmaf(A.w, d0.y, d1.y));
    s[t] = v;
    __syncthreads();

    #pragma unroll
    for (int k = 0; k < 10; k++) {
        const int o = 1 << k;
        float4 P = sP[k];
        float2 u = (t >= o) ? s[t - o] : make_float2(0.0f, 0.0f);
        __syncthreads();
        if (t >= o) {
            v.x = fmaf(P.x, u.x, fmaf(P.y, u.y, v.x));
            v.y = fmaf(P.z, u.x, fmaf(P.w, u.y, v.y));
        }
        s[t] = v;
        __syncthreads();
    }

    // s[t] = true end state of chunk 2t+1.
    float2 Ep = (t == 0) ? make_float2(0.0f, 0.0f) : s[t - 1];
    float2 i1;   // init of chunk 2t+1 = end of chunk 2t = d0 + A*Ep
    i1.x = fmaf(A.x, Ep.x, fmaf(A.y, Ep.y, d0.x));
    i1.y = fmaf(A.z, Ep.x, fmaf(A.w, Ep.y, d0.y));
    g_init[row * CPR + 2 * t]     = Ep;
    g_init[row * CPR + 2 * t + 1] = i1;
}

// ---------------------------------------------------------------------------
// Phase 3: replay from true initial state; clip*gain in place in the warp's
// staging region, then warp-cooperative streamed store.
__global__ void __launch_bounds__(CPB, 8)
phase3_kernel(const float* __restrict__ x, float* __restrict__ out,
              const float* __restrict__ ac, const float* __restrict__ bcf,
              const float* __restrict__ gain)
{
    __shared__ float sb[CPB / 32][32 * WIN];

    const int t    = threadIdx.x;
    const int wu   = t >> 5;
    const int lane = t & 31;
    const int bg   = blockIdx.x * CPB;
    const int g    = bg + t;
    const int row  = bg >> 11;
    const int bcc  = bg & (CPR - 1);
    const int cir  = bcc + t;

    const float a0 = __ldg(&ac[0]);
    const float a1 = __ldg(&ac[1]) / a0, a2 = __ldg(&ac[2]) / a0;
    const float b0 = __ldg(&bcf[0]) / a0, b1 = __ldg(&bcf[1]) / a0,
                b2 = __ldg(&bcf[2]) / a0;
    const float na1 = -a1, na2 = -a2;
    const float c00 = fmaf(a1, a1, -a2);
    const float c01 = a1 * a2;
    const float gn  = __ldg(&gain[0]);

    const float* xr   = x + (size_t)row * TLEN;
    const float4* xw4 =
        (const float4*)(xr + (size_t)(bcc + wu * 32) * CHUNK);
    float4* ow4 =
        (float4*)(out + (size_t)row * TLEN + (size_t)(bcc + wu * 32) * CHUNK);
    float* sw = &sb[wu][0];

    float x1 = 0.0f, x2 = 0.0f;
    if (cir > 0) { int n0 = cir * CHUNK; x1 = xr[n0 - 1]; x2 = xr[n0 - 2]; }

    float2 ini = __ldg(&g_init[g]);
    float y1 = ini.x, y2 = ini.y;

    for (int w = 0; w < NW; w++) {
        #pragma unroll
        for (int j = 0; j < 8; j++) {
            int idx = lane + 32 * j;
            int c   = idx >> 3;
            int sl  = idx & 7;
            float4 v = __ldg(xw4 + c * (CHUNK / 4) + w * 8 + sl);
            *(float4*)&sw[c * WIN + (((sl + c) & 7) << 2)] = v;
        }
        __syncwarp();

        float* rowp = &sw[lane * WIN];
        #pragma unroll
        for (int gq = 0; gq < 8; gq++) {
            float4* slot = (float4*)&rowp[((gq + lane) & 7) << 2];
            float4 v = *slot;
            float4 o;
            {
                float f0 = fmaf(b2, x2, fmaf(b1, x1, b0 * v.x));
                float f1 = fmaf(b2, x1, fmaf(b1, v.x, b0 * v.y));
                float F1 = fmaf(na1, f0, f1);
                float t0 = fmaf(na2, y2, f0);
                float t1 = fmaf(c01, y2, F1);
                float yA = fmaf(na1, y1, t0);
                float yB = fmaf(c00, y1, t1);
                y2 = yA; y1 = yB; x2 = v.x; x1 = v.y;
                o.x = fminf(fmaxf(yA, -1.0f), 1.0f) * gn;
                o.y = fminf(fmaxf(yB, -1.0f), 1.0f) * gn;
            }
            {
                float f0 = fmaf(b2, x2, fmaf(b1, x1, b0 * v.z));
                float f1 = fmaf(b2, x1, fmaf(b1, v.z, b0 * v.w));
                float F1 = fmaf(na1, f0, f1);
                float t0 = fmaf(na2, y2, f0);
                float t1 = fmaf(c01, y2, F1);
                float yA = fmaf(na1, y1, t0);
                float yB = fmaf(c00, y1, t1);
                y2 = yA; y1 = yB; x2 = v.z; x1 = v.w;
                o.z = fminf(fmaxf(yA, -1.0f), 1.0f) * gn;
                o.w = fminf(fmaxf(yB, -1.0f), 1.0f) * gn;
            }
            *slot = o;   // in-place: own row only
        }
        __syncwarp();

        // warp-cooperative streamed store of this warp's window
        #pragma unroll
        for (int j = 0; j < 8; j++) {
            int idx = lane + 32 * j;
            int c   = idx >> 3;
            int sl  = idx & 7;
            float4 v = *(const float4*)&sw[c * WIN + (((sl + c) & 7) << 2)];
            __stcs(ow4 + c * (CHUNK / 4) + w * 8 + sl, v);
        }
        __syncwarp();   // stores' smem reads done before next window's fill
    }
}

// ---------------------------------------------------------------------------
extern "C" void kernel_launch(void* const* d_in, const int* in_sizes, int n_in,
                              void* d_out, int out_size)
{
    const float* x    = (const float*)d_in[0];
    const float* a    = (const float*)d_in[1];
    const float* b    = (const float*)d_in[2];
    const float* gain = (const float*)d_in[3];
    float* out = (float*)d_out;

    phase1_kernel<<<NBLK, CPB>>>(x, a, b);
    phase2_kernel<<<BATCH, 1024>>>(a);
    phase3_kernel<<<NBLK, CPB>>>(x, out, a, b, gain);
}

// round 9
// speedup vs baseline: 1.2536x; 1.0246x over previous
#include <cuda_runtime.h>

// ModelFilter: y = gain * clip(IIR2(FIR2(x)), -1, 1)
// 3-kernel chunked parallel scan, per-warp staging, CHUNK=64 for full
// register-capped residency (262144 chunk-threads).
//   phase1: zero-IC chunk end states (step-2 companion form recurrence)
//   phase2: per-row scan, 4 chunks/thread fold + Kogge-Stone (closed-form
//           fp64 matrix powers)
//   phase3: replay from true init (x re-read hits L2), clip*gain, stcs out.

#define BATCH 64
#define TLEN  262144
#define CHUNK 64
#define CPR   (TLEN / CHUNK)          // 4096 chunks per row
#define TOTAL_CHUNKS (BATCH * CPR)    // 262144
#define CPB   128                     // chunk-threads per block (4 warps)
#define NBLK  (TOTAL_CHUNKS / CPB)    // 2048 blocks
#define WIN   32                      // samples per window = 128B smem row
#define NW    (CHUNK / WIN)           // 2 windows

__device__ float2 g_d[TOTAL_CHUNKS];     // phase-1 zero-IC end states
__device__ float2 g_init[TOTAL_CHUNKS];  // phase-2 true initial states

// ---------------------------------------------------------------------------
// Phase 1: zero-IC chunk recurrence -> end states. Per-warp staging.
__global__ void __launch_bounds__(CPB, 8)
phase1_kernel(const float* __restrict__ x,
              const float* __restrict__ ac,
              const float* __restrict__ bcf)
{
    __shared__ float sb[CPB / 32][32 * WIN];    // 4 KB per warp

    const int t    = threadIdx.x;
    const int wu   = t >> 5;
    const int lane = t & 31;
    const int bg   = blockIdx.x * CPB;
    const int g    = bg + t;
    const int row  = bg >> 12;                  // CPR = 4096
    const int bcc  = bg & (CPR - 1);
    const int cir  = bcc + t;

    const float a0 = __ldg(&ac[0]);
    const float a1 = __ldg(&ac[1]) / a0, a2 = __ldg(&ac[2]) / a0;
    const float b0 = __ldg(&bcf[0]) / a0, b1 = __ldg(&bcf[1]) / a0,
                b2 = __ldg(&bcf[2]) / a0;
    const float na1 = -a1, na2 = -a2;
    const float c00 = fmaf(a1, a1, -a2);        // a1^2 - a2
    const float c01 = a1 * a2;

    const float* xr   = x + (size_t)row * TLEN;
    const float4* xw4 =
        (const float4*)(xr + (size_t)(bcc + wu * 32) * CHUNK);
    float* sw = &sb[wu][0];

    float x1 = 0.0f, x2 = 0.0f;
    if (cir > 0) { int n0 = cir * CHUNK; x1 = xr[n0 - 1]; x2 = xr[n0 - 2]; }
    float y1 = 0.0f, y2 = 0.0f;

    for (int w = 0; w < NW; w++) {
        // warp-cooperative coalesced load of this warp's 32 chunks' window
        #pragma unroll
        for (int j = 0; j < 8; j++) {
            int idx = lane + 32 * j;
            int c   = idx >> 3;
            int sl  = idx & 7;
            float4 v = __ldg(xw4 + c * (CHUNK / 4) + w * 8 + sl);
            *(float4*)&sw[c * WIN + (((sl + c) & 7) << 2)] = v;
        }
        __syncwarp();

        const float* rowp = &sw[lane * WIN];
        #pragma unroll
        for (int gq = 0; gq < 8; gq++) {
            float4 v = *(const float4*)&rowp[((gq + lane) & 7) << 2];
            {
                float f0 = fmaf(b2, x2, fmaf(b1, x1, b0 * v.x));
                float f1 = fmaf(b2, x1, fmaf(b1, v.x, b0 * v.y));
                float F1 = fmaf(na1, f0, f1);
                float t0 = fmaf(na2, y2, f0);
                float t1 = fmaf(c01, y2, F1);
                float yA = fmaf(na1, y1, t0);
                float yB = fmaf(c00, y1, t1);
                y2 = yA; y1 = yB; x2 = v.x; x1 = v.y;
            }
            {
                float f0 = fmaf(b2, x2, fmaf(b1, x1, b0 * v.z));
                float f1 = fmaf(b2, x1, fmaf(b1, v.z, b0 * v.w));
                float F1 = fmaf(na1, f0, f1);
                float t0 = fmaf(na2, y2, f0);
                float t1 = fmaf(c01, y2, F1);
                float yA = fmaf(na1, y1, t0);
                float yB = fmaf(c00, y1, t1);
                y2 = yA; y1 = yB; x2 = v.z; x1 = v.w;
            }
        }
        __syncwarp();   // all lanes done reading before next window's stores
    }
    g_d[g] = make_float2(y1, y2);
}

// ---------------------------------------------------------------------------
// Phase 2: per-row scan, 4096 chunks/row. 1024 threads, 4 chunks/thread:
// serial fold with A = M^64, 10-level Kogge-Stone with powers of B = A^4.
// Closed-form fp64 powers:
//   M^n = [[U_n, -a2*U_{n-1}], [U_{n-1}, -a2*U_{n-2}]],
//   U_m = r^m sin((m+1)theta)/sin(theta), r = sqrt(a2), cos(theta)=-a1/(2r).
__global__ void __launch_bounds__(1024)
phase2_kernel(const float* __restrict__ ac)
{
    __shared__ float2 s[1024];
    __shared__ float4 sA;
    __shared__ float4 sP[10];

    const int t   = threadIdx.x;
    const int row = blockIdx.x;

    if (t <= 10) {
        double a0 = (double)ac[0];
        double a1 = (double)ac[1] / a0;
        double a2 = (double)ac[2] / a0;
        double r  = sqrt(a2);
        double ct = -a1 / (2.0 * r);
        double th = acos(ct);
        double st = sqrt(fmax(1.0 - ct * ct, 1e-300));
        double n  = (t < 10) ? (double)(256 << t) : 64.0;  // sP[k]=M^(256*2^k); sA=M^64
        double rn1 = exp((n - 1.0) * log(r));              // r^(n-1)
        double Sn  = sin(n * th) / st;
        double Snp = sin((n + 1.0) * th) / st;
        double Snm = sin((n - 1.0) * th) / st;
        float4 P;
        P.x = (float)( rn1 * r * Snp);
        P.y = (float)(-rn1 * r * r * Sn);
        P.z = (float)( rn1 * Sn);
        P.w = (float)(-rn1 * r * Snm);
        if (t < 10) sP[t] = P; else sA = P;
    }
    __syncthreads();

    const float4 A = sA;
    // load 4 chunk states (2 x float4 = 4 x float2, 16B aligned)
    const float4* dp = (const float4*)&g_d[row * CPR + 4 * t];
    float4 q0 = dp[0], q1 = dp[1];
    float2 d0 = make_float2(q0.x, q0.y), d1 = make_float2(q0.z, q0.w);
    float2 d2 = make_float2(q1.x, q1.y), d3 = make_float2(q1.z, q1.w);

    // fold: v = ((d0*A + d1)*A + d2)*A + d3   (v = A*v + d_next)
    float2 v = d0;
    #define MV(dn) { float2 nv; \
        nv.x = fmaf(A.x, v.x, fmaf(A.y, v.y, dn.x)); \
        nv.y = fmaf(A.z, v.x, fmaf(A.w, v.y, dn.y)); v = nv; }
    MV(d1) MV(d2) MV(d3)
    s[t] = v;
    __syncthreads();

    #pragma unroll
    for (int k = 0; k < 10; k++) {
        const int o = 1 << k;
        float4 P = sP[k];
        float2 u = (t >= o) ? s[t - o] : make_float2(0.0f, 0.0f);
        __syncthreads();
        if (t >= o) {
            v.x = fmaf(P.x, u.x, fmaf(P.y, u.y, v.x));
            v.y = fmaf(P.z, u.x, fmaf(P.w, u.y, v.y));
        }
        s[t] = v;
        __syncthreads();
    }

    // exclusive prefix (true entering state of chunk 4t), then walk forward
    float2 i0 = (t == 0) ? make_float2(0.0f, 0.0f) : s[t - 1];
    float2 i1, i2, i3;
    i1.x = fmaf(A.x, i0.x, fmaf(A.y, i0.y, d0.x));
    i1.y = fmaf(A.z, i0.x, fmaf(A.w, i0.y, d0.y));
    i2.x = fmaf(A.x, i1.x, fmaf(A.y, i1.y, d1.x));
    i2.y = fmaf(A.z, i1.x, fmaf(A.w, i1.y, d1.y));
    i3.x = fmaf(A.x, i2.x, fmaf(A.y, i2.y, d2.x));
    i3.y = fmaf(A.z, i2.x, fmaf(A.w, i2.y, d2.y));

    float4* ip = (float4*)&g_init[row * CPR + 4 * t];
    ip[0] = make_float4(i0.x, i0.y, i1.x, i1.y);
    ip[1] = make_float4(i2.x, i2.y, i3.x, i3.y);
    #undef MV
}

// ---------------------------------------------------------------------------
// Phase 3: replay from true initial state; clip*gain in place in the warp's
// staging region, then warp-cooperative streamed store.
__global__ void __launch_bounds__(CPB, 8)
phase3_kernel(const float* __restrict__ x, float* __restrict__ out,
              const float* __restrict__ ac, const float* __restrict__ bcf,
              const float* __restrict__ gain)
{
    __shared__ float sb[CPB / 32][32 * WIN];

    const int t    = threadIdx.x;
    const int wu   = t >> 5;
    const int lane = t & 31;
    const int bg   = blockIdx.x * CPB;
    const int g    = bg + t;
    const int row  = bg >> 12;
    const int bcc  = bg & (CPR - 1);
    const int cir  = bcc + t;

    const float a0 = __ldg(&ac[0]);
    const float a1 = __ldg(&ac[1]) / a0, a2 = __ldg(&ac[2]) / a0;
    const float b0 = __ldg(&bcf[0]) / a0, b1 = __ldg(&bcf[1]) / a0,
                b2 = __ldg(&bcf[2]) / a0;
    const float na1 = -a1, na2 = -a2;
    const float c00 = fmaf(a1, a1, -a2);
    const float c01 = a1 * a2;
    const float gn  = __ldg(&gain[0]);

    const float* xr   = x + (size_t)row * TLEN;
    const float4* xw4 =
        (const float4*)(xr + (size_t)(bcc + wu * 32) * CHUNK);
    float4* ow4 =
        (float4*)(out + (size_t)row * TLEN + (size_t)(bcc + wu * 32) * CHUNK);
    float* sw = &sb[wu][0];

    float x1 = 0.0f, x2 = 0.0f;
    if (cir > 0) { int n0 = cir * CHUNK; x1 = xr[n0 - 1]; x2 = xr[n0 - 2]; }

    float2 ini = __ldg(&g_init[g]);
    float y1 = ini.x, y2 = ini.y;

    for (int w = 0; w < NW; w++) {
        #pragma unroll
        for (int j = 0; j < 8; j++) {
            int idx = lane + 32 * j;
            int c   = idx >> 3;
            int sl  = idx & 7;
            float4 v = __ldg(xw4 + c * (CHUNK / 4) + w * 8 + sl);
            *(float4*)&sw[c * WIN + (((sl + c) & 7) << 2)] = v;
        }
        __syncwarp();

        float* rowp = &sw[lane * WIN];
        #pragma unroll
        for (int gq = 0; gq < 8; gq++) {
            float4* slot = (float4*)&rowp[((gq + lane) & 7) << 2];
            float4 v = *slot;
            float4 o;
            {
                float f0 = fmaf(b2, x2, fmaf(b1, x1, b0 * v.x));
                float f1 = fmaf(b2, x1, fmaf(b1, v.x, b0 * v.y));
                float F1 = fmaf(na1, f0, f1);
                float t0 = fmaf(na2, y2, f0);
                float t1 = fmaf(c01, y2, F1);
                float yA = fmaf(na1, y1, t0);
                float yB = fmaf(c00, y1, t1);
                y2 = yA; y1 = yB; x2 = v.x; x1 = v.y;
                o.x = fminf(fmaxf(yA, -1.0f), 1.0f) * gn;
                o.y = fminf(fmaxf(yB, -1.0f), 1.0f) * gn;
            }
            {
                float f0 = fmaf(b2, x2, fmaf(b1, x1, b0 * v.z));
                float f1 = fmaf(b2, x1, fmaf(b1, v.z, b0 * v.w));
                float F1 = fmaf(na1, f0, f1);
                float t0 = fmaf(na2, y2, f0);
                float t1 = fmaf(c01, y2, F1);
                float yA = fmaf(na1, y1, t0);
                float yB = fmaf(c00, y1, t1);
                y2 = yA; y1 = yB; x2 = v.z; x1 = v.w;
                o.z = fminf(fmaxf(yA, -1.0f), 1.0f) * gn;
                o.w = fminf(fmaxf(yB, -1.0f), 1.0f) * gn;
            }
            *slot = o;   // in-place: own row only
        }
        __syncwarp();

        // warp-cooperative streamed store of this warp's window
        #pragma unroll
        for (int j = 0; j < 8; j++) {
            int idx = lane + 32 * j;
            int c   = idx >> 3;
            int sl  = idx & 7;
            float4 v = *(const float4*)&sw[c * WIN + (((sl + c) & 7) << 2)];
            __stcs(ow4 + c * (CHUNK / 4) + w * 8 + sl, v);
        }
        __syncwarp();   // stores' smem reads done before next window's fill
    }
}

// ---------------------------------------------------------------------------
extern "C" void kernel_launch(void* const* d_in, const int* in_sizes, int n_in,
                              void* d_out, int out_size)
{
    const float* x    = (const float*)d_in[0];
    const float* a    = (const float*)d_in[1];
    const float* b    = (const float*)d_in[2];
    const float* gain = (const float*)d_in[3];
    float* out = (float*)d_out;

    phase1_kernel<<<NBLK, CPB>>>(x, a, b);
    phase2_kernel<<<BATCH, 1024>>>(a);
    phase3_kernel<<<NBLK, CPB>>>(x, out, a, b, gain);
}